// round 13
// baseline (speedup 1.0000x reference)
#include <cuda_runtime.h>
#include <cuda_bf16.h>
#include <cstdint>

#define N_NODES 100000
#define N_EDGES 600000
#define DIM 128
#define KTOT 640   // 512 (4 bases x 128) + 128 (root)
#define SCAN_BLOCKS 98
#define SCAT_BLOCKS 586   // ceil(600000/1024)
#define AGG_BLOCKS 12500

// ---------------- scratch (zero-initialized at load; re-zeroed by cleanup) ----------------
__device__ float g_h1[(size_t)N_NODES * DIM];
__device__ __nv_bfloat16 g_A1hi[(size_t)N_NODES * KTOT];
__device__ __nv_bfloat16 g_A1lo[(size_t)N_NODES * KTOT];
__device__ __nv_bfloat16 g_A2hi[(size_t)N_NODES * KTOT];
__device__ __nv_bfloat16 g_A2lo[(size_t)N_NODES * KTOT];
__device__ float4 g_coeff1[N_EDGES];
__device__ float4 g_coeff2[N_EDGES];
__device__ int   g_csr_src[N_EDGES];
__device__ int   g_csr_esrc[N_EDGES];
__device__ int   g_deg[N_NODES];                          // 0 at entry
__device__ int   g_rowptr[N_NODES + 1];
__device__ int   g_cursor[N_NODES];
__device__ float g_invdeg[N_NODES];
__device__ unsigned long long g_scan_state[SCAN_BLOCKS];  // 0 at entry
__device__ int   g_ticket;                                // 0 at entry
__device__ int   g_scan_done;                             // 0 at entry
__device__ __nv_bfloat16 g_Whi[128 * KTOT];
__device__ __nv_bfloat16 g_Wlo[128 * KTOT];
__device__ __nv_bfloat16 g_W2hi[128 * KTOT];
__device__ __nv_bfloat16 g_W2lo[128 * KTOT];

// ---------------- helpers ----------------
__device__ __forceinline__ uint32_t smem_u32(const void* p) {
    uint32_t a;
    asm("{ .reg .u64 t; cvta.to.shared.u64 t, %1; cvt.u32.u64 %0, t; }" : "=r"(a) : "l"(p));
    return a;
}
__device__ __forceinline__ void ldm_x4(uint32_t* r, uint32_t addr) {
    asm volatile("ldmatrix.sync.aligned.m8n8.x4.shared.b16 {%0,%1,%2,%3}, [%4];"
                 : "=r"(r[0]), "=r"(r[1]), "=r"(r[2]), "=r"(r[3]) : "r"(addr));
}
__device__ __forceinline__ void mma16816(float* c, const uint32_t* a, const uint32_t* b) {
    asm volatile("mma.sync.aligned.m16n8k16.row.col.f32.bf16.bf16.f32 "
                 "{%0,%1,%2,%3}, {%4,%5,%6,%7}, {%8,%9}, {%0,%1,%2,%3};"
                 : "+f"(c[0]), "+f"(c[1]), "+f"(c[2]), "+f"(c[3])
                 : "r"(a[0]), "r"(a[1]), "r"(a[2]), "r"(a[3]), "r"(b[0]), "r"(b[1]));
}
__device__ __forceinline__ void cp16(uint32_t dst, const void* src) {
    asm volatile("cp.async.cg.shared.global [%0], [%1], 16;" :: "r"(dst), "l"(src));
}
#define CP_COMMIT() asm volatile("cp.async.commit_group;" ::: "memory")
#define CP_WAIT(N)  asm volatile("cp.async.wait_group %0;" :: "n"(N) : "memory")

// packed hi/lo split via cvt.rn.bf16x2.f32
__device__ __forceinline__ void pack_hilo(float a, float b, uint32_t& uh, uint32_t& ul) {
    uint32_t h;
    asm("cvt.rn.bf16x2.f32 %0, %1, %2;" : "=r"(h) : "f"(b), "f"(a));
    float ha = __uint_as_float(h << 16);
    float hb = __uint_as_float(h & 0xFFFF0000u);
    float la = a - ha;
    float lb = b - hb;
    asm("cvt.rn.bf16x2.f32 %0, %1, %2;" : "=r"(ul) : "f"(lb), "f"(la));
    uh = h;
}

// ---------------- 1: hist + weight split ----------------
__global__ void k_hist_prepw(const int* __restrict__ dst,
                             const float* __restrict__ basis1, const float* __restrict__ root1,
                             const float* __restrict__ basis2, const float* __restrict__ root2) {
    int i = blockIdx.x * blockDim.x + threadIdx.x;
    if (i == 0) g_rowptr[N_NODES] = N_EDGES;
    if (i < N_EDGES) atomicAdd(&g_deg[dst[i]], 1);
    if (i < 2 * 128 * KTOT) {
        int which = i >= 128 * KTOT;
        int idx = which ? i - 128 * KTOT : i;
        int n = idx / KTOT;
        int k = idx % KTOT;
        const float* basis = which ? basis2 : basis1;
        const float* root  = which ? root2  : root1;
        float w = (k < 512) ? basis[(size_t)k * 128 + n] : root[(size_t)(k - 512) * 128 + n];
        __nv_bfloat16 hi = __float2bfloat16(w);
        __nv_bfloat16 lo = __float2bfloat16(w - __bfloat162float(hi));
        if (which) { g_W2hi[n * KTOT + k] = hi; g_W2lo[n * KTOT + k] = lo; }
        else       { g_Whi[n * KTOT + k]  = hi; g_Wlo[n * KTOT + k]  = lo; }
    }
}

// ---------------- 2: fused scan + scatter ----------------
__global__ __launch_bounds__(1024) void k_csr(
    const int* __restrict__ dst, const int* __restrict__ src,
    const int* __restrict__ entity,
    const int* __restrict__ etype, const float* __restrict__ enorm,
    const float4* __restrict__ att1, const float4* __restrict__ att2) {
    __shared__ int sh[1024];
    __shared__ int sbid;
    __shared__ int sexcl;
    int t = threadIdx.x;
    if (t == 0) sbid = atomicAdd(&g_ticket, 1);
    __syncthreads();
    int b = sbid;

    if (b < SCAN_BLOCKS) {
        int i = b * 1024 + t;
        int v = (i < N_NODES) ? g_deg[i] : 0;
        sh[t] = v;
        __syncthreads();
        #pragma unroll
        for (int off = 1; off < 1024; off <<= 1) {
            int x = (t >= off) ? sh[t - off] : 0;
            __syncthreads();
            sh[t] += x;
            __syncthreads();
        }
        if (t == 0) {
            int total = sh[1023];
            int excl = 0;
            if (b == 0) {
                atomicExch(&g_scan_state[0], ((unsigned long long)total << 2) | 2ull);
            } else {
                atomicExch(&g_scan_state[b], ((unsigned long long)total << 2) | 1ull);
                int j = b - 1;
                long long run = 0;
                while (true) {
                    unsigned long long s = atomicAdd(&g_scan_state[j], 0ull);
                    unsigned f = (unsigned)(s & 3ull);
                    if (f == 0) continue;
                    run += (long long)(s >> 2);
                    if (f == 2) break;
                    j--;
                }
                excl = (int)run;
                atomicExch(&g_scan_state[b], ((unsigned long long)(excl + total) << 2) | 2ull);
            }
            sexcl = excl;
        }
        __syncthreads();
        int i2 = b * 1024 + t;
        if (i2 < N_NODES) {
            int rp = sexcl + sh[t] - g_deg[i2];
            g_rowptr[i2] = rp;
            g_cursor[i2] = rp;
            g_invdeg[i2] = 1.0f / fmaxf((float)g_deg[i2], 1.0f);
        }
        __syncthreads();
        if (t == 0) {
            __threadfence();
            atomicAdd(&g_scan_done, 1);
        }
    } else {
        if (t == 0) {
            while (atomicAdd(&g_scan_done, 0) < SCAN_BLOCKS) { }
        }
        __syncthreads();
        __threadfence();
        int e = (b - SCAN_BLOCKS) * 1024 + t;
        if (e < N_EDGES) {
            int s = src[e];
            int pos = atomicAdd(&g_cursor[dst[e]], 1);
            g_csr_src[pos] = s;
            g_csr_esrc[pos] = entity[s];
            int ty = etype[e];
            float n = enorm[e];
            float4 a1 = att1[ty];
            float4 a2 = att2[ty];
            g_coeff1[pos] = make_float4(a1.x * n, a1.y * n, a1.z * n, a1.w * n);
            g_coeff2[pos] = make_float4(a2.x * n, a2.y * n, a2.z * n, a2.w * n);
        }
    }
}

// ---------------- aggregation core (R4/R8-proven) ----------------
__device__ __forceinline__ void agg_node(int node, int lane,
                                         const float4* __restrict__ X4,
                                         const int* __restrict__ sidx,
                                         const float4* __restrict__ cf,
                                         float4& s0, float4& s1, float4& s2, float4& s3) {
    int beg = g_rowptr[node], end = g_rowptr[node + 1];
    int p = beg;
    for (; p + 2 <= end; p += 2) {
        float4 ca = cf[p];
        float4 cb = cf[p + 1];
        int sa = sidx[p];
        int sb = sidx[p + 1];
        float4 xa = X4[(size_t)sa * 32 + lane];
        float4 xb = X4[(size_t)sb * 32 + lane];
        s0.x = fmaf(ca.x, xa.x, s0.x); s0.y = fmaf(ca.x, xa.y, s0.y);
        s0.z = fmaf(ca.x, xa.z, s0.z); s0.w = fmaf(ca.x, xa.w, s0.w);
        s1.x = fmaf(ca.y, xa.x, s1.x); s1.y = fmaf(ca.y, xa.y, s1.y);
        s1.z = fmaf(ca.y, xa.z, s1.z); s1.w = fmaf(ca.y, xa.w, s1.w);
        s2.x = fmaf(ca.z, xa.x, s2.x); s2.y = fmaf(ca.z, xa.y, s2.y);
        s2.z = fmaf(ca.z, xa.z, s2.z); s2.w = fmaf(ca.z, xa.w, s2.w);
        s3.x = fmaf(ca.w, xa.x, s3.x); s3.y = fmaf(ca.w, xa.y, s3.y);
        s3.z = fmaf(ca.w, xa.z, s3.z); s3.w = fmaf(ca.w, xa.w, s3.w);
        s0.x = fmaf(cb.x, xb.x, s0.x); s0.y = fmaf(cb.x, xb.y, s0.y);
        s0.z = fmaf(cb.x, xb.z, s0.z); s0.w = fmaf(cb.x, xb.w, s0.w);
        s1.x = fmaf(cb.y, xb.x, s1.x); s1.y = fmaf(cb.y, xb.y, s1.y);
        s1.z = fmaf(cb.y, xb.z, s1.z); s1.w = fmaf(cb.y, xb.w, s1.w);
        s2.x = fmaf(cb.z, xb.x, s2.x); s2.y = fmaf(cb.z, xb.y, s2.y);
        s2.z = fmaf(cb.z, xb.z, s2.z); s2.w = fmaf(cb.z, xb.w, s2.w);
        s3.x = fmaf(cb.w, xb.x, s3.x); s3.y = fmaf(cb.w, xb.y, s3.y);
        s3.z = fmaf(cb.w, xb.z, s3.z); s3.w = fmaf(cb.w, xb.w, s3.w);
    }
    if (p < end) {
        float4 c = cf[p];
        int sn = sidx[p];
        float4 xv = X4[(size_t)sn * 32 + lane];
        s0.x = fmaf(c.x, xv.x, s0.x); s0.y = fmaf(c.x, xv.y, s0.y);
        s0.z = fmaf(c.x, xv.z, s0.z); s0.w = fmaf(c.x, xv.w, s0.w);
        s1.x = fmaf(c.y, xv.x, s1.x); s1.y = fmaf(c.y, xv.y, s1.y);
        s1.z = fmaf(c.y, xv.z, s1.z); s1.w = fmaf(c.y, xv.w, s1.w);
        s2.x = fmaf(c.z, xv.x, s2.x); s2.y = fmaf(c.z, xv.y, s2.y);
        s2.z = fmaf(c.z, xv.z, s2.z); s2.w = fmaf(c.z, xv.w, s2.w);
        s3.x = fmaf(c.w, xv.x, s3.x); s3.y = fmaf(c.w, xv.y, s3.y);
        s3.z = fmaf(c.w, xv.z, s3.z); s3.w = fmaf(c.w, xv.w, s3.w);
    }
}

__device__ __forceinline__ void agg_store(int node, int lane, float d,
                                          float4 s0, float4 s1, float4 s2, float4 s3,
                                          __nv_bfloat16* Ahi, __nv_bfloat16* Alo) {
    s0.x *= d; s0.y *= d; s0.z *= d; s0.w *= d;
    s1.x *= d; s1.y *= d; s1.z *= d; s1.w *= d;
    s2.x *= d; s2.y *= d; s2.z *= d; s2.w *= d;
    s3.x *= d; s3.y *= d; s3.z *= d; s3.w *= d;
    size_t base = (size_t)node * KTOT + 4 * lane;
    uint2 uh, ul;
    pack_hilo(s0.x, s0.y, uh.x, ul.x); pack_hilo(s0.z, s0.w, uh.y, ul.y);
    *(uint2*)(Ahi + base) = uh; *(uint2*)(Alo + base) = ul;
    pack_hilo(s1.x, s1.y, uh.x, ul.x); pack_hilo(s1.z, s1.w, uh.y, ul.y);
    *(uint2*)(Ahi + base + 128) = uh; *(uint2*)(Alo + base + 128) = ul;
    pack_hilo(s2.x, s2.y, uh.x, ul.x); pack_hilo(s2.z, s2.w, uh.y, ul.y);
    *(uint2*)(Ahi + base + 256) = uh; *(uint2*)(Alo + base + 256) = ul;
    pack_hilo(s3.x, s3.y, uh.x, ul.x); pack_hilo(s3.z, s3.w, uh.y, ul.y);
    *(uint2*)(Ahi + base + 384) = uh; *(uint2*)(Alo + base + 384) = ul;
}

// ---------------- 3: layer-1 aggregation ----------------
__global__ void k_agg0(const float4* __restrict__ tbl, const int* __restrict__ entity) {
    int gw = (blockIdx.x * blockDim.x + threadIdx.x) >> 5;
    int lane = threadIdx.x & 31;
    if (gw >= N_NODES) return;
    float4 s0 = make_float4(0.f, 0.f, 0.f, 0.f);
    float4 s1 = s0, s2 = s0, s3 = s0;
    agg_node(gw, lane, tbl, g_csr_esrc, g_coeff1, s0, s1, s2, s3);
    agg_store(gw, lane, g_invdeg[gw], s0, s1, s2, s3, g_A1hi, g_A1lo);
    float4 xs = tbl[(size_t)entity[gw] * 32 + lane];
    size_t a = (size_t)gw * KTOT + 512 + 4 * lane;
    uint2 uh, ul;
    pack_hilo(xs.x, xs.y, uh.x, ul.x); pack_hilo(xs.z, xs.w, uh.y, ul.y);
    *(uint2*)(g_A1hi + a) = uh; *(uint2*)(g_A1lo + a) = ul;
}

// ---------------- 5: layer-2 aggregation + relation_emb + cleanup ----------------
#define REL_BLOCKS 32
#define CLEAN_BLOCKS 391
__global__ void k_agg1(const float* __restrict__ rel, float* __restrict__ out) {
    if (blockIdx.x >= AGG_BLOCKS + REL_BLOCKS) {
        int i = (blockIdx.x - AGG_BLOCKS - REL_BLOCKS) * 256 + threadIdx.x;
        if (i < N_NODES) g_deg[i] = 0;
        if (i < SCAN_BLOCKS) g_scan_state[i] = 0ull;
        if (i == 0) { g_ticket = 0; g_scan_done = 0; }
        return;
    }
    if (blockIdx.x >= AGG_BLOCKS) {
        int i = (blockIdx.x - AGG_BLOCKS) * 256 + threadIdx.x;
        for (; i < 500 * 128; i += REL_BLOCKS * 256)
            out[(size_t)N_NODES * 128 + i] = rel[i];
        return;
    }
    int gw = (blockIdx.x * blockDim.x + threadIdx.x) >> 5;
    int lane = threadIdx.x & 31;
    if (gw >= N_NODES) return;
    float4 s0 = make_float4(0.f, 0.f, 0.f, 0.f);
    float4 s1 = s0, s2 = s0, s3 = s0;
    agg_node(gw, lane, (const float4*)g_h1, g_csr_src, g_coeff2, s0, s1, s2, s3);
    agg_store(gw, lane, g_invdeg[gw], s0, s1, s2, s3, g_A2hi, g_A2lo);
}

// ---------------- 4/6: HMMA GEMM, 4 warps, warp tile 64x64 (6:1 MMA:LDSM) ----------------
#define TILE_B 10240
#define BUF_B  (4 * TILE_B)
#define SMEM_GEMM (2 * BUF_B)   // 81920

__global__ __launch_bounds__(128) void k_gemm_mma(
    int layer, const float* __restrict__ bias, float* __restrict__ out_param, int do_relu)
{
    extern __shared__ char smem[];
    uint32_t sbase = smem_u32(smem);
    const __nv_bfloat16* Ahi = (layer == 0) ? g_A1hi : g_A2hi;
    const __nv_bfloat16* Alo = (layer == 0) ? g_A1lo : g_A2lo;
    const __nv_bfloat16* Whi = (layer == 0) ? g_Whi : g_W2hi;
    const __nv_bfloat16* Wlo = (layer == 0) ? g_Wlo : g_W2lo;
    float* out = (layer == 0) ? g_h1 : out_param;

    int tid = threadIdx.x;
    int wid = tid >> 5;
    int lane = tid & 31;
    int bm = blockIdx.x * 128;
    int wm0 = (wid >> 1) * 64;   // 2 M-groups
    int wn0 = (wid & 1) * 64;    // 2 N-groups

    float acc[4][8][4];
    #pragma unroll
    for (int i = 0; i < 4; i++)
        #pragma unroll
        for (int j = 0; j < 8; j++)
            #pragma unroll
            for (int q = 0; q < 4; q++) acc[i][j][q] = 0.f;

    // loader: 128 threads, one row each, 4 x 16B chunks per tile
    int lr = tid;
    int gmr = bm + lr; if (gmr >= N_NODES) gmr = 0;
    uint32_t a_off = (uint32_t)(lane & 15) * 80 + (uint32_t)(lane >> 4) * 16;
    int bg = lane >> 3;
    uint32_t b_off = (uint32_t)((bg >> 1) * 8 + (lane & 7)) * 80 + (uint32_t)(bg & 1) * 16;

    auto load_chunk = [&](int ch, int buf) {
        int kc = ch * 32;
        uint32_t bo = sbase + buf * BUF_B;
        uint32_t drow = (uint32_t)lr * 80;
        #pragma unroll
        for (int cc = 0; cc < 4; cc++) {
            uint32_t dof = drow + cc * 16;
            int eof = kc + cc * 8;
            cp16(bo + dof,              Ahi + (size_t)gmr * KTOT + eof);
            cp16(bo + TILE_B + dof,     Alo + (size_t)gmr * KTOT + eof);
            cp16(bo + 2 * TILE_B + dof, Whi + lr * KTOT + eof);
            cp16(bo + 3 * TILE_B + dof, Wlo + lr * KTOT + eof);
        }
    };

    load_chunk(0, 0);
    CP_COMMIT();

    #pragma unroll 1
    for (int ch = 0; ch < 20; ch++) {
        int buf = ch & 1;
        if (ch < 19) {
            load_chunk(ch + 1, buf ^ 1);
            CP_COMMIT();
            CP_WAIT(1);
        } else {
            CP_WAIT(0);
        }
        __syncthreads();

        uint32_t a_hi_base = sbase + buf * BUF_B;
        uint32_t a_lo_base = a_hi_base + TILE_B;
        uint32_t b_hi_base = a_hi_base + 2 * TILE_B;
        uint32_t b_lo_base = a_hi_base + 3 * TILE_B;

        #pragma unroll
        for (int kk = 0; kk < 2; kk++) {
            uint32_t kb = (uint32_t)kk * 32;
            uint32_t ahi[4][4], alo[4][4];
            #pragma unroll
            for (int mf = 0; mf < 4; mf++) {
                uint32_t o = (uint32_t)(wm0 + mf * 16) * 80 + a_off + kb;
                ldm_x4(ahi[mf], a_hi_base + o);
                ldm_x4(alo[mf], a_lo_base + o);
            }
            uint32_t bhi[8][2], blo[8][2];
            #pragma unroll
            for (int pr = 0; pr < 4; pr++) {
                uint32_t o = (uint32_t)(wn0 + pr * 16) * 80 + b_off + kb;
                uint32_t th[4], tl[4];
                ldm_x4(th, b_hi_base + o);
                ldm_x4(tl, b_lo_base + o);
                bhi[pr * 2][0] = th[0]; bhi[pr * 2][1] = th[1];
                bhi[pr * 2 + 1][0] = th[2]; bhi[pr * 2 + 1][1] = th[3];
                blo[pr * 2][0] = tl[0]; blo[pr * 2][1] = tl[1];
                blo[pr * 2 + 1][0] = tl[2]; blo[pr * 2 + 1][1] = tl[3];
            }
            #pragma unroll
            for (int mf = 0; mf < 4; mf++)
                #pragma unroll
                for (int nf = 0; nf < 8; nf++) {
                    mma16816(acc[mf][nf], ahi[mf], bhi[nf]);
                    mma16816(acc[mf][nf], ahi[mf], blo[nf]);
                    mma16816(acc[mf][nf], alo[mf], bhi[nf]);
                }
        }
        __syncthreads();
    }

    int qm = lane >> 2;
    int qn = (lane & 3) * 2;
    #pragma unroll
    for (int nf = 0; nf < 8; nf++) {
        int n = wn0 + nf * 8 + qn;
        float b0 = bias[n], b1 = bias[n + 1];
        #pragma unroll
        for (int mf = 0; mf < 4; mf++) {
            int m0 = bm + wm0 + mf * 16 + qm;
            float2 lo = make_float2(acc[mf][nf][0] + b0, acc[mf][nf][1] + b1);
            float2 hi = make_float2(acc[mf][nf][2] + b0, acc[mf][nf][3] + b1);
            if (do_relu) {
                lo.x = fmaxf(lo.x, 0.f); lo.y = fmaxf(lo.y, 0.f);
                hi.x = fmaxf(hi.x, 0.f); hi.y = fmaxf(hi.y, 0.f);
            }
            if (m0 < N_NODES) {
                *(float2*)(out + (size_t)m0 * 128 + n) = lo;
                if (layer == 0) {
                    size_t a = (size_t)m0 * KTOT + 512 + n;
                    uint32_t uh, ul;
                    pack_hilo(lo.x, lo.y, uh, ul);
                    *(uint32_t*)(g_A2hi + a) = uh;
                    *(uint32_t*)(g_A2lo + a) = ul;
                }
            }
            if (m0 + 8 < N_NODES) {
                *(float2*)(out + (size_t)(m0 + 8) * 128 + n) = hi;
                if (layer == 0) {
                    size_t a = (size_t)(m0 + 8) * KTOT + 512 + n;
                    uint32_t uh, ul;
                    pack_hilo(hi.x, hi.y, uh, ul);
                    *(uint32_t*)(g_A2hi + a) = uh;
                    *(uint32_t*)(g_A2lo + a) = ul;
                }
            }
        }
    }
}

// ---------------- launch ----------------
extern "C" void kernel_launch(void* const* d_in, const int* in_sizes, int n_in,
                              void* d_out, int out_size) {
    const int*   entity       = (const int*)d_in[0];
    const int*   edge_index   = (const int*)d_in[1];
    const int*   edge_type    = (const int*)d_in[2];
    const float* edge_norm    = (const float*)d_in[3];
    // d_in[4] = DAD_rel (unused by reference output)
    const float* entity_table = (const float*)d_in[5];
    const float* relation_emb = (const float*)d_in[6];
    const float* basis1 = (const float*)d_in[7];
    const float* att1   = (const float*)d_in[8];
    const float* root1  = (const float*)d_in[9];
    const float* bias1  = (const float*)d_in[10];
    const float* basis2 = (const float*)d_in[11];
    const float* att2   = (const float*)d_in[12];
    const float* root2  = (const float*)d_in[13];
    const float* bias2  = (const float*)d_in[14];

    const int* src = edge_index;
    const int* dst = edge_index + N_EDGES;
    float* out = (float*)d_out;

    static int smem_set = 0;
    if (!smem_set) {
        cudaFuncSetAttribute(k_gemm_mma, cudaFuncAttributeMaxDynamicSharedMemorySize, SMEM_GEMM);
        smem_set = 1;
    }

    int gemm_blocks = (N_NODES + 127) / 128;   // 782

    // 1: histogram + weight split
    k_hist_prepw<<<(N_EDGES + 255) / 256, 256>>>(dst, basis1, root1, basis2, root2);
    // 2: fused scan + scatter
    k_csr<<<SCAN_BLOCKS + SCAT_BLOCKS, 1024>>>(dst, src, entity, edge_type, edge_norm,
                                               (const float4*)att1, (const float4*)att2);
    // 3: layer-1 aggregation
    k_agg0<<<AGG_BLOCKS, 256>>>((const float4*)entity_table, entity);
    // 4: layer-1 GEMM (relu) -> h1 + A2 root cols   [PROFILED SLOT]
    k_gemm_mma<<<gemm_blocks, 128, SMEM_GEMM>>>(0, bias1, nullptr, 1);
    // 5: layer-2 aggregation + relation_emb + cleanup
    k_agg1<<<AGG_BLOCKS + REL_BLOCKS + CLEAN_BLOCKS, 256>>>(relation_emb, out);
    // 6: layer-2 GEMM (no relu) -> d_out
    k_gemm_mma<<<gemm_blocks, 128, SMEM_GEMM>>>(1, bias2, out, 0);
}

// round 14
// speedup vs baseline: 1.1347x; 1.1347x over previous
#include <cuda_runtime.h>
#include <cuda_bf16.h>
#include <cstdint>

#define N_NODES 100000
#define N_EDGES 600000
#define DIM 128
#define KTOT 640   // 512 (4 bases x 128) + 128 (root)
#define SCAN_BLOCKS 98
#define SCAT_BLOCKS 586   // ceil(600000/1024)
#define AGG_BLOCKS 12500

// ---------------- scratch (zero-initialized at load; re-zeroed by cleanup) ----------------
__device__ float g_h1[(size_t)N_NODES * DIM];
__device__ __nv_bfloat16 g_A1hi[(size_t)N_NODES * KTOT];
__device__ __nv_bfloat16 g_A1lo[(size_t)N_NODES * KTOT];
__device__ __nv_bfloat16 g_A2hi[(size_t)N_NODES * KTOT];
__device__ __nv_bfloat16 g_A2lo[(size_t)N_NODES * KTOT];
__device__ float4 g_coeff1[N_EDGES];
__device__ float4 g_coeff2[N_EDGES];
__device__ int   g_csr_src[N_EDGES];
__device__ int   g_csr_esrc[N_EDGES];
__device__ int   g_deg[N_NODES];                          // 0 at entry
__device__ int   g_rowptr[N_NODES + 1];
__device__ int   g_cursor[N_NODES];
__device__ float g_invdeg[N_NODES];
__device__ unsigned long long g_scan_state[SCAN_BLOCKS];  // 0 at entry
__device__ int   g_ticket;                                // 0 at entry
__device__ int   g_scan_done;                             // 0 at entry
__device__ __nv_bfloat16 g_Whi[128 * KTOT];
__device__ __nv_bfloat16 g_Wlo[128 * KTOT];
__device__ __nv_bfloat16 g_W2hi[128 * KTOT];
__device__ __nv_bfloat16 g_W2lo[128 * KTOT];

// ---------------- helpers ----------------
__device__ __forceinline__ uint32_t smem_u32(const void* p) {
    uint32_t a;
    asm("{ .reg .u64 t; cvta.to.shared.u64 t, %1; cvt.u32.u64 %0, t; }" : "=r"(a) : "l"(p));
    return a;
}
__device__ __forceinline__ void ldm_x4(uint32_t* r, uint32_t addr) {
    asm volatile("ldmatrix.sync.aligned.m8n8.x4.shared.b16 {%0,%1,%2,%3}, [%4];"
                 : "=r"(r[0]), "=r"(r[1]), "=r"(r[2]), "=r"(r[3]) : "r"(addr));
}
__device__ __forceinline__ void mma16816(float* c, const uint32_t* a, const uint32_t* b) {
    asm volatile("mma.sync.aligned.m16n8k16.row.col.f32.bf16.bf16.f32 "
                 "{%0,%1,%2,%3}, {%4,%5,%6,%7}, {%8,%9}, {%0,%1,%2,%3};"
                 : "+f"(c[0]), "+f"(c[1]), "+f"(c[2]), "+f"(c[3])
                 : "r"(a[0]), "r"(a[1]), "r"(a[2]), "r"(a[3]), "r"(b[0]), "r"(b[1]));
}
__device__ __forceinline__ void cp16(uint32_t dst, const void* src) {
    asm volatile("cp.async.cg.shared.global [%0], [%1], 16;" :: "r"(dst), "l"(src));
}
#define CP_COMMIT() asm volatile("cp.async.commit_group;" ::: "memory")
#define CP_WAIT(N)  asm volatile("cp.async.wait_group %0;" :: "n"(N) : "memory")

// packed hi/lo split via cvt.rn.bf16x2.f32
__device__ __forceinline__ void pack_hilo(float a, float b, uint32_t& uh, uint32_t& ul) {
    uint32_t h;
    asm("cvt.rn.bf16x2.f32 %0, %1, %2;" : "=r"(h) : "f"(b), "f"(a));
    float ha = __uint_as_float(h << 16);
    float hb = __uint_as_float(h & 0xFFFF0000u);
    float la = a - ha;
    float lb = b - hb;
    asm("cvt.rn.bf16x2.f32 %0, %1, %2;" : "=r"(ul) : "f"(lb), "f"(la));
    uh = h;
}

// ---------------- 1: hist + weight split ----------------
__global__ void k_hist_prepw(const int* __restrict__ dst,
                             const float* __restrict__ basis1, const float* __restrict__ root1,
                             const float* __restrict__ basis2, const float* __restrict__ root2) {
    int i = blockIdx.x * blockDim.x + threadIdx.x;
    if (i == 0) g_rowptr[N_NODES] = N_EDGES;
    if (i < N_EDGES) atomicAdd(&g_deg[dst[i]], 1);
    if (i < 2 * 128 * KTOT) {
        int which = i >= 128 * KTOT;
        int idx = which ? i - 128 * KTOT : i;
        int n = idx / KTOT;
        int k = idx % KTOT;
        const float* basis = which ? basis2 : basis1;
        const float* root  = which ? root2  : root1;
        float w = (k < 512) ? basis[(size_t)k * 128 + n] : root[(size_t)(k - 512) * 128 + n];
        __nv_bfloat16 hi = __float2bfloat16(w);
        __nv_bfloat16 lo = __float2bfloat16(w - __bfloat162float(hi));
        if (which) { g_W2hi[n * KTOT + k] = hi; g_W2lo[n * KTOT + k] = lo; }
        else       { g_Whi[n * KTOT + k]  = hi; g_Wlo[n * KTOT + k]  = lo; }
    }
}

// ---------------- 2: fused scan + scatter ----------------
__global__ __launch_bounds__(1024) void k_csr(
    const int* __restrict__ dst, const int* __restrict__ src,
    const int* __restrict__ entity,
    const int* __restrict__ etype, const float* __restrict__ enorm,
    const float4* __restrict__ att1, const float4* __restrict__ att2) {
    __shared__ int sh[1024];
    __shared__ int sbid;
    __shared__ int sexcl;
    int t = threadIdx.x;
    if (t == 0) sbid = atomicAdd(&g_ticket, 1);
    __syncthreads();
    int b = sbid;

    if (b < SCAN_BLOCKS) {
        int i = b * 1024 + t;
        int v = (i < N_NODES) ? g_deg[i] : 0;
        sh[t] = v;
        __syncthreads();
        #pragma unroll
        for (int off = 1; off < 1024; off <<= 1) {
            int x = (t >= off) ? sh[t - off] : 0;
            __syncthreads();
            sh[t] += x;
            __syncthreads();
        }
        if (t == 0) {
            int total = sh[1023];
            int excl = 0;
            if (b == 0) {
                atomicExch(&g_scan_state[0], ((unsigned long long)total << 2) | 2ull);
            } else {
                atomicExch(&g_scan_state[b], ((unsigned long long)total << 2) | 1ull);
                int j = b - 1;
                long long run = 0;
                while (true) {
                    unsigned long long s = atomicAdd(&g_scan_state[j], 0ull);
                    unsigned f = (unsigned)(s & 3ull);
                    if (f == 0) continue;
                    run += (long long)(s >> 2);
                    if (f == 2) break;
                    j--;
                }
                excl = (int)run;
                atomicExch(&g_scan_state[b], ((unsigned long long)(excl + total) << 2) | 2ull);
            }
            sexcl = excl;
        }
        __syncthreads();
        int i2 = b * 1024 + t;
        if (i2 < N_NODES) {
            int rp = sexcl + sh[t] - g_deg[i2];
            g_rowptr[i2] = rp;
            g_cursor[i2] = rp;
            g_invdeg[i2] = 1.0f / fmaxf((float)g_deg[i2], 1.0f);
        }
        __syncthreads();
        if (t == 0) {
            __threadfence();
            atomicAdd(&g_scan_done, 1);
        }
    } else {
        if (t == 0) {
            while (atomicAdd(&g_scan_done, 0) < SCAN_BLOCKS) { }
        }
        __syncthreads();
        __threadfence();
        int e = (b - SCAN_BLOCKS) * 1024 + t;
        if (e < N_EDGES) {
            int s = src[e];
            int pos = atomicAdd(&g_cursor[dst[e]], 1);
            g_csr_src[pos] = s;
            g_csr_esrc[pos] = entity[s];
            int ty = etype[e];
            float n = enorm[e];
            float4 a1 = att1[ty];
            float4 a2 = att2[ty];
            g_coeff1[pos] = make_float4(a1.x * n, a1.y * n, a1.z * n, a1.w * n);
            g_coeff2[pos] = make_float4(a2.x * n, a2.y * n, a2.z * n, a2.w * n);
        }
    }
}

// ---------------- aggregation core (R4/R8-proven) ----------------
__device__ __forceinline__ void agg_node(int node, int lane,
                                         const float4* __restrict__ X4,
                                         const int* __restrict__ sidx,
                                         const float4* __restrict__ cf,
                                         float4& s0, float4& s1, float4& s2, float4& s3) {
    int beg = g_rowptr[node], end = g_rowptr[node + 1];
    int p = beg;
    for (; p + 2 <= end; p += 2) {
        float4 ca = cf[p];
        float4 cb = cf[p + 1];
        int sa = sidx[p];
        int sb = sidx[p + 1];
        float4 xa = X4[(size_t)sa * 32 + lane];
        float4 xb = X4[(size_t)sb * 32 + lane];
        s0.x = fmaf(ca.x, xa.x, s0.x); s0.y = fmaf(ca.x, xa.y, s0.y);
        s0.z = fmaf(ca.x, xa.z, s0.z); s0.w = fmaf(ca.x, xa.w, s0.w);
        s1.x = fmaf(ca.y, xa.x, s1.x); s1.y = fmaf(ca.y, xa.y, s1.y);
        s1.z = fmaf(ca.y, xa.z, s1.z); s1.w = fmaf(ca.y, xa.w, s1.w);
        s2.x = fmaf(ca.z, xa.x, s2.x); s2.y = fmaf(ca.z, xa.y, s2.y);
        s2.z = fmaf(ca.z, xa.z, s2.z); s2.w = fmaf(ca.z, xa.w, s2.w);
        s3.x = fmaf(ca.w, xa.x, s3.x); s3.y = fmaf(ca.w, xa.y, s3.y);
        s3.z = fmaf(ca.w, xa.z, s3.z); s3.w = fmaf(ca.w, xa.w, s3.w);
        s0.x = fmaf(cb.x, xb.x, s0.x); s0.y = fmaf(cb.x, xb.y, s0.y);
        s0.z = fmaf(cb.x, xb.z, s0.z); s0.w = fmaf(cb.x, xb.w, s0.w);
        s1.x = fmaf(cb.y, xb.x, s1.x); s1.y = fmaf(cb.y, xb.y, s1.y);
        s1.z = fmaf(cb.y, xb.z, s1.z); s1.w = fmaf(cb.y, xb.w, s1.w);
        s2.x = fmaf(cb.z, xb.x, s2.x); s2.y = fmaf(cb.z, xb.y, s2.y);
        s2.z = fmaf(cb.z, xb.z, s2.z); s2.w = fmaf(cb.z, xb.w, s2.w);
        s3.x = fmaf(cb.w, xb.x, s3.x); s3.y = fmaf(cb.w, xb.y, s3.y);
        s3.z = fmaf(cb.w, xb.z, s3.z); s3.w = fmaf(cb.w, xb.w, s3.w);
    }
    if (p < end) {
        float4 c = cf[p];
        int sn = sidx[p];
        float4 xv = X4[(size_t)sn * 32 + lane];
        s0.x = fmaf(c.x, xv.x, s0.x); s0.y = fmaf(c.x, xv.y, s0.y);
        s0.z = fmaf(c.x, xv.z, s0.z); s0.w = fmaf(c.x, xv.w, s0.w);
        s1.x = fmaf(c.y, xv.x, s1.x); s1.y = fmaf(c.y, xv.y, s1.y);
        s1.z = fmaf(c.y, xv.z, s1.z); s1.w = fmaf(c.y, xv.w, s1.w);
        s2.x = fmaf(c.z, xv.x, s2.x); s2.y = fmaf(c.z, xv.y, s2.y);
        s2.z = fmaf(c.z, xv.z, s2.z); s2.w = fmaf(c.z, xv.w, s2.w);
        s3.x = fmaf(c.w, xv.x, s3.x); s3.y = fmaf(c.w, xv.y, s3.y);
        s3.z = fmaf(c.w, xv.z, s3.z); s3.w = fmaf(c.w, xv.w, s3.w);
    }
}

__device__ __forceinline__ void agg_store(int node, int lane, float d,
                                          float4 s0, float4 s1, float4 s2, float4 s3,
                                          __nv_bfloat16* Ahi, __nv_bfloat16* Alo) {
    s0.x *= d; s0.y *= d; s0.z *= d; s0.w *= d;
    s1.x *= d; s1.y *= d; s1.z *= d; s1.w *= d;
    s2.x *= d; s2.y *= d; s2.z *= d; s2.w *= d;
    s3.x *= d; s3.y *= d; s3.z *= d; s3.w *= d;
    size_t base = (size_t)node * KTOT + 4 * lane;
    uint2 uh, ul;
    pack_hilo(s0.x, s0.y, uh.x, ul.x); pack_hilo(s0.z, s0.w, uh.y, ul.y);
    *(uint2*)(Ahi + base) = uh; *(uint2*)(Alo + base) = ul;
    pack_hilo(s1.x, s1.y, uh.x, ul.x); pack_hilo(s1.z, s1.w, uh.y, ul.y);
    *(uint2*)(Ahi + base + 128) = uh; *(uint2*)(Alo + base + 128) = ul;
    pack_hilo(s2.x, s2.y, uh.x, ul.x); pack_hilo(s2.z, s2.w, uh.y, ul.y);
    *(uint2*)(Ahi + base + 256) = uh; *(uint2*)(Alo + base + 256) = ul;
    pack_hilo(s3.x, s3.y, uh.x, ul.x); pack_hilo(s3.z, s3.w, uh.y, ul.y);
    *(uint2*)(Ahi + base + 384) = uh; *(uint2*)(Alo + base + 384) = ul;
}

// ---------------- 3: layer-1 aggregation ----------------
__global__ void k_agg0(const float4* __restrict__ tbl, const int* __restrict__ entity) {
    int gw = (blockIdx.x * blockDim.x + threadIdx.x) >> 5;
    int lane = threadIdx.x & 31;
    if (gw >= N_NODES) return;
    float4 s0 = make_float4(0.f, 0.f, 0.f, 0.f);
    float4 s1 = s0, s2 = s0, s3 = s0;
    agg_node(gw, lane, tbl, g_csr_esrc, g_coeff1, s0, s1, s2, s3);
    agg_store(gw, lane, g_invdeg[gw], s0, s1, s2, s3, g_A1hi, g_A1lo);
    float4 xs = tbl[(size_t)entity[gw] * 32 + lane];
    size_t a = (size_t)gw * KTOT + 512 + 4 * lane;
    uint2 uh, ul;
    pack_hilo(xs.x, xs.y, uh.x, ul.x); pack_hilo(xs.z, xs.w, uh.y, ul.y);
    *(uint2*)(g_A1hi + a) = uh; *(uint2*)(g_A1lo + a) = ul;
}

// ---------------- 5: layer-2 aggregation + relation_emb + cleanup ----------------
#define REL_BLOCKS 32
#define CLEAN_BLOCKS 391
__global__ void k_agg1(const float* __restrict__ rel, float* __restrict__ out) {
    if (blockIdx.x >= AGG_BLOCKS + REL_BLOCKS) {
        int i = (blockIdx.x - AGG_BLOCKS - REL_BLOCKS) * 256 + threadIdx.x;
        if (i < N_NODES) g_deg[i] = 0;
        if (i < SCAN_BLOCKS) g_scan_state[i] = 0ull;
        if (i == 0) { g_ticket = 0; g_scan_done = 0; }
        return;
    }
    if (blockIdx.x >= AGG_BLOCKS) {
        int i = (blockIdx.x - AGG_BLOCKS) * 256 + threadIdx.x;
        for (; i < 500 * 128; i += REL_BLOCKS * 256)
            out[(size_t)N_NODES * 128 + i] = rel[i];
        return;
    }
    int gw = (blockIdx.x * blockDim.x + threadIdx.x) >> 5;
    int lane = threadIdx.x & 31;
    if (gw >= N_NODES) return;
    float4 s0 = make_float4(0.f, 0.f, 0.f, 0.f);
    float4 s1 = s0, s2 = s0, s3 = s0;
    agg_node(gw, lane, (const float4*)g_h1, g_csr_src, g_coeff2, s0, s1, s2, s3);
    agg_store(gw, lane, g_invdeg[gw], s0, s1, s2, s3, g_A2hi, g_A2lo);
}

// ---------------- 4/6: HMMA GEMM (R12 tiling; 3 hazard-free MMA sweeps) ----------------
#define TILE_B 10240
#define BUF_B  (4 * TILE_B)
#define SMEM_GEMM (2 * BUF_B)   // 81920 -> 2 CTAs/SM

__global__ __launch_bounds__(256) void k_gemm_mma(
    int layer, const float* __restrict__ bias, float* __restrict__ out_param, int do_relu)
{
    extern __shared__ char smem[];
    uint32_t sbase = smem_u32(smem);
    const __nv_bfloat16* Ahi = (layer == 0) ? g_A1hi : g_A2hi;
    const __nv_bfloat16* Alo = (layer == 0) ? g_A1lo : g_A2lo;
    const __nv_bfloat16* Whi = (layer == 0) ? g_Whi : g_W2hi;
    const __nv_bfloat16* Wlo = (layer == 0) ? g_Wlo : g_W2lo;
    float* out = (layer == 0) ? g_h1 : out_param;

    int tid = threadIdx.x;
    int wid = tid >> 5;
    int lane = tid & 31;
    int bm = blockIdx.x * 128;
    int wm0 = (wid >> 2) * 64;
    int wn0 = (wid & 3) * 32;

    float acc[4][4][4];
    #pragma unroll
    for (int i = 0; i < 4; i++)
        #pragma unroll
        for (int j = 0; j < 4; j++)
            #pragma unroll
            for (int q = 0; q < 4; q++) acc[i][j][q] = 0.f;

    int lr = tid >> 1;
    int lc0 = (tid & 1) * 2;
    int gmr = bm + lr; if (gmr >= N_NODES) gmr = 0;
    uint32_t a_off = (uint32_t)(lane & 15) * 80 + (uint32_t)(lane >> 4) * 16;
    int bg = lane >> 3;
    uint32_t b_off = (uint32_t)((bg >> 1) * 8 + (lane & 7)) * 80 + (uint32_t)(bg & 1) * 16;

    auto load_chunk = [&](int ch, int buf) {
        int kc = ch * 32;
        uint32_t bo = sbase + buf * BUF_B;
        uint32_t drow = (uint32_t)lr * 80;
        #pragma unroll
        for (int c = 0; c < 2; c++) {
            int cc = lc0 + c;
            uint32_t dof = drow + cc * 16;
            int eof = kc + cc * 8;
            cp16(bo + dof,              Ahi + (size_t)gmr * KTOT + eof);
            cp16(bo + TILE_B + dof,     Alo + (size_t)gmr * KTOT + eof);
            cp16(bo + 2 * TILE_B + dof, Whi + lr * KTOT + eof);
            cp16(bo + 3 * TILE_B + dof, Wlo + lr * KTOT + eof);
        }
    };

    load_chunk(0, 0);
    CP_COMMIT();

    #pragma unroll 1
    for (int ch = 0; ch < 20; ch++) {
        int buf = ch & 1;
        if (ch < 19) {
            load_chunk(ch + 1, buf ^ 1);
            CP_COMMIT();
            CP_WAIT(1);
        } else {
            CP_WAIT(0);
        }
        __syncthreads();

        uint32_t a_hi_base = sbase + buf * BUF_B;
        uint32_t a_lo_base = a_hi_base + TILE_B;
        uint32_t b_hi_base = a_hi_base + 2 * TILE_B;
        uint32_t b_lo_base = a_hi_base + 3 * TILE_B;

        #pragma unroll
        for (int kk = 0; kk < 2; kk++) {
            uint32_t kb = (uint32_t)kk * 32;
            uint32_t ahi[4][4], alo[4][4];
            #pragma unroll
            for (int mf = 0; mf < 4; mf++) {
                uint32_t o = (uint32_t)(wm0 + mf * 16) * 80 + a_off + kb;
                ldm_x4(ahi[mf], a_hi_base + o);
                ldm_x4(alo[mf], a_lo_base + o);
            }
            uint32_t bhi[4][2], blo[4][2];
            #pragma unroll
            for (int pr = 0; pr < 2; pr++) {
                uint32_t o = (uint32_t)(wn0 + pr * 16) * 80 + b_off + kb;
                uint32_t th[4], tl[4];
                ldm_x4(th, b_hi_base + o);
                ldm_x4(tl, b_lo_base + o);
                bhi[pr * 2][0] = th[0]; bhi[pr * 2][1] = th[1];
                bhi[pr * 2 + 1][0] = th[2]; bhi[pr * 2 + 1][1] = th[3];
                blo[pr * 2][0] = tl[0]; blo[pr * 2][1] = tl[1];
                blo[pr * 2 + 1][0] = tl[2]; blo[pr * 2 + 1][1] = tl[3];
            }
            // 3 hazard-free sweeps: each accumulator touched once per sweep,
            // reuse distance 16 MMAs (vs 1 in the fused form).
            #pragma unroll
            for (int mf = 0; mf < 4; mf++)
                #pragma unroll
                for (int nf = 0; nf < 4; nf++)
                    mma16816(acc[mf][nf], ahi[mf], bhi[nf]);
            #pragma unroll
            for (int mf = 0; mf < 4; mf++)
                #pragma unroll
                for (int nf = 0; nf < 4; nf++)
                    mma16816(acc[mf][nf], ahi[mf], blo[nf]);
            #pragma unroll
            for (int mf = 0; mf < 4; mf++)
                #pragma unroll
                for (int nf = 0; nf < 4; nf++)
                    mma16816(acc[mf][nf], alo[mf], bhi[nf]);
        }
        __syncthreads();
    }

    int qm = lane >> 2;
    int qn = (lane & 3) * 2;
    #pragma unroll
    for (int nf = 0; nf < 4; nf++) {
        int n = wn0 + nf * 8 + qn;
        float b0 = bias[n], b1 = bias[n + 1];
        #pragma unroll
        for (int mf = 0; mf < 4; mf++) {
            int m0 = bm + wm0 + mf * 16 + qm;
            float2 lo = make_float2(acc[mf][nf][0] + b0, acc[mf][nf][1] + b1);
            float2 hi = make_float2(acc[mf][nf][2] + b0, acc[mf][nf][3] + b1);
            if (do_relu) {
                lo.x = fmaxf(lo.x, 0.f); lo.y = fmaxf(lo.y, 0.f);
                hi.x = fmaxf(hi.x, 0.f); hi.y = fmaxf(hi.y, 0.f);
            }
            if (m0 < N_NODES) {
                *(float2*)(out + (size_t)m0 * 128 + n) = lo;
                if (layer == 0) {
                    size_t a = (size_t)m0 * KTOT + 512 + n;
                    uint32_t uh, ul;
                    pack_hilo(lo.x, lo.y, uh, ul);
                    *(uint32_t*)(g_A2hi + a) = uh;
                    *(uint32_t*)(g_A2lo + a) = ul;
                }
            }
            if (m0 + 8 < N_NODES) {
                *(float2*)(out + (size_t)(m0 + 8) * 128 + n) = hi;
                if (layer == 0) {
                    size_t a = (size_t)(m0 + 8) * KTOT + 512 + n;
                    uint32_t uh, ul;
                    pack_hilo(hi.x, hi.y, uh, ul);
                    *(uint32_t*)(g_A2hi + a) = uh;
                    *(uint32_t*)(g_A2lo + a) = ul;
                }
            }
        }
    }
}

// ---------------- launch ----------------
extern "C" void kernel_launch(void* const* d_in, const int* in_sizes, int n_in,
                              void* d_out, int out_size) {
    const int*   entity       = (const int*)d_in[0];
    const int*   edge_index   = (const int*)d_in[1];
    const int*   edge_type    = (const int*)d_in[2];
    const float* edge_norm    = (const float*)d_in[3];
    // d_in[4] = DAD_rel (unused by reference output)
    const float* entity_table = (const float*)d_in[5];
    const float* relation_emb = (const float*)d_in[6];
    const float* basis1 = (const float*)d_in[7];
    const float* att1   = (const float*)d_in[8];
    const float* root1  = (const float*)d_in[9];
    const float* bias1  = (const float*)d_in[10];
    const float* basis2 = (const float*)d_in[11];
    const float* att2   = (const float*)d_in[12];
    const float* root2  = (const float*)d_in[13];
    const float* bias2  = (const float*)d_in[14];

    const int* src = edge_index;
    const int* dst = edge_index + N_EDGES;
    float* out = (float*)d_out;

    static int smem_set = 0;
    if (!smem_set) {
        cudaFuncSetAttribute(k_gemm_mma, cudaFuncAttributeMaxDynamicSharedMemorySize, SMEM_GEMM);
        smem_set = 1;
    }

    int gemm_blocks = (N_NODES + 127) / 128;   // 782

    // 1: histogram + weight split
    k_hist_prepw<<<(N_EDGES + 255) / 256, 256>>>(dst, basis1, root1, basis2, root2);
    // 2: fused scan + scatter
    k_csr<<<SCAN_BLOCKS + SCAT_BLOCKS, 1024>>>(dst, src, entity, edge_type, edge_norm,
                                               (const float4*)att1, (const float4*)att2);
    // 3: layer-1 aggregation
    k_agg0<<<AGG_BLOCKS, 256>>>((const float4*)entity_table, entity);
    // 4: layer-1 GEMM (relu) -> h1 + A2 root cols   [PROFILED SLOT]
    k_gemm_mma<<<gemm_blocks, 256, SMEM_GEMM>>>(0, bias1, nullptr, 1);
    // 5: layer-2 aggregation + relation_emb + cleanup
    k_agg1<<<AGG_BLOCKS + REL_BLOCKS + CLEAN_BLOCKS, 256>>>(relation_emb, out);
    // 6: layer-2 GEMM (no relu) -> d_out
    k_gemm_mma<<<gemm_blocks, 256, SMEM_GEMM>>>(1, bias2, out, 0);
}

// round 15
// speedup vs baseline: 1.1383x; 1.0032x over previous
#include <cuda_runtime.h>
#include <cuda_bf16.h>
#include <cstdint>

#define N_NODES 100000
#define N_EDGES 600000
#define DIM 128
#define KTOT 640   // 512 (4 bases x 128) + 128 (root)
#define SCAN_BLOCKS 98
#define SCAT_BLOCKS 586   // ceil(600000/1024)
#define AGG_BLOCKS 12500

// ---------------- scratch (zero-initialized at load; re-zeroed by cleanup) ----------------
__device__ float g_h1[(size_t)N_NODES * DIM];
__device__ __nv_bfloat16 g_A1hi[(size_t)N_NODES * KTOT];
__device__ __nv_bfloat16 g_A1lo[(size_t)N_NODES * KTOT];
__device__ __nv_bfloat16 g_A2hi[(size_t)N_NODES * KTOT];
__device__ __nv_bfloat16 g_A2lo[(size_t)N_NODES * KTOT];
__device__ float4 g_coeff1[N_EDGES];
__device__ float4 g_coeff2[N_EDGES];
__device__ int   g_csr_src[N_EDGES];
__device__ int   g_csr_esrc[N_EDGES];
__device__ int   g_deg[N_NODES];                          // 0 at entry
__device__ int   g_rowptr[N_NODES + 1];
__device__ int   g_cursor[N_NODES];
__device__ float g_invdeg[N_NODES];
__device__ unsigned long long g_scan_state[SCAN_BLOCKS];  // 0 at entry
__device__ int   g_ticket;                                // 0 at entry
__device__ int   g_scan_done;                             // 0 at entry
__device__ __nv_bfloat16 g_Whi[128 * KTOT];
__device__ __nv_bfloat16 g_Wlo[128 * KTOT];
__device__ __nv_bfloat16 g_W2hi[128 * KTOT];
__device__ __nv_bfloat16 g_W2lo[128 * KTOT];

// ---------------- helpers ----------------
__device__ __forceinline__ uint32_t smem_u32(const void* p) {
    uint32_t a;
    asm("{ .reg .u64 t; cvta.to.shared.u64 t, %1; cvt.u32.u64 %0, t; }" : "=r"(a) : "l"(p));
    return a;
}
__device__ __forceinline__ void ldm_x4(uint32_t* r, uint32_t addr) {
    asm volatile("ldmatrix.sync.aligned.m8n8.x4.shared.b16 {%0,%1,%2,%3}, [%4];"
                 : "=r"(r[0]), "=r"(r[1]), "=r"(r[2]), "=r"(r[3]) : "r"(addr));
}
__device__ __forceinline__ void mma16816(float* c, const uint32_t* a, const uint32_t* b) {
    asm volatile("mma.sync.aligned.m16n8k16.row.col.f32.bf16.bf16.f32 "
                 "{%0,%1,%2,%3}, {%4,%5,%6,%7}, {%8,%9}, {%0,%1,%2,%3};"
                 : "+f"(c[0]), "+f"(c[1]), "+f"(c[2]), "+f"(c[3])
                 : "r"(a[0]), "r"(a[1]), "r"(a[2]), "r"(a[3]), "r"(b[0]), "r"(b[1]));
}
__device__ __forceinline__ void cp16(uint32_t dst, const void* src) {
    asm volatile("cp.async.cg.shared.global [%0], [%1], 16;" :: "r"(dst), "l"(src));
}
#define CP_COMMIT() asm volatile("cp.async.commit_group;" ::: "memory")
#define CP_WAIT(N)  asm volatile("cp.async.wait_group %0;" :: "n"(N) : "memory")

// packed hi/lo split via cvt.rn.bf16x2.f32
__device__ __forceinline__ void pack_hilo(float a, float b, uint32_t& uh, uint32_t& ul) {
    uint32_t h;
    asm("cvt.rn.bf16x2.f32 %0, %1, %2;" : "=r"(h) : "f"(b), "f"(a));
    float ha = __uint_as_float(h << 16);
    float hb = __uint_as_float(h & 0xFFFF0000u);
    float la = a - ha;
    float lb = b - hb;
    asm("cvt.rn.bf16x2.f32 %0, %1, %2;" : "=r"(ul) : "f"(lb), "f"(la));
    uh = h;
}

// ---------------- 1: hist + weight split ----------------
__global__ void k_hist_prepw(const int* __restrict__ dst,
                             const float* __restrict__ basis1, const float* __restrict__ root1,
                             const float* __restrict__ basis2, const float* __restrict__ root2) {
    int i = blockIdx.x * blockDim.x + threadIdx.x;
    if (i == 0) g_rowptr[N_NODES] = N_EDGES;
    if (i < N_EDGES) atomicAdd(&g_deg[dst[i]], 1);
    if (i < 2 * 128 * KTOT) {
        int which = i >= 128 * KTOT;
        int idx = which ? i - 128 * KTOT : i;
        int n = idx / KTOT;
        int k = idx % KTOT;
        const float* basis = which ? basis2 : basis1;
        const float* root  = which ? root2  : root1;
        float w = (k < 512) ? basis[(size_t)k * 128 + n] : root[(size_t)(k - 512) * 128 + n];
        __nv_bfloat16 hi = __float2bfloat16(w);
        __nv_bfloat16 lo = __float2bfloat16(w - __bfloat162float(hi));
        if (which) { g_W2hi[n * KTOT + k] = hi; g_W2lo[n * KTOT + k] = lo; }
        else       { g_Whi[n * KTOT + k]  = hi; g_Wlo[n * KTOT + k]  = lo; }
    }
}

// ---------------- 2: fused scan + scatter ----------------
__global__ __launch_bounds__(1024) void k_csr(
    const int* __restrict__ dst, const int* __restrict__ src,
    const int* __restrict__ entity,
    const int* __restrict__ etype, const float* __restrict__ enorm,
    const float4* __restrict__ att1, const float4* __restrict__ att2) {
    __shared__ int sh[1024];
    __shared__ int sbid;
    __shared__ int sexcl;
    int t = threadIdx.x;
    if (t == 0) sbid = atomicAdd(&g_ticket, 1);
    __syncthreads();
    int b = sbid;

    if (b < SCAN_BLOCKS) {
        int i = b * 1024 + t;
        int v = (i < N_NODES) ? g_deg[i] : 0;
        sh[t] = v;
        __syncthreads();
        #pragma unroll
        for (int off = 1; off < 1024; off <<= 1) {
            int x = (t >= off) ? sh[t - off] : 0;
            __syncthreads();
            sh[t] += x;
            __syncthreads();
        }
        if (t == 0) {
            int total = sh[1023];
            int excl = 0;
            if (b == 0) {
                atomicExch(&g_scan_state[0], ((unsigned long long)total << 2) | 2ull);
            } else {
                atomicExch(&g_scan_state[b], ((unsigned long long)total << 2) | 1ull);
                int j = b - 1;
                long long run = 0;
                while (true) {
                    unsigned long long s = atomicAdd(&g_scan_state[j], 0ull);
                    unsigned f = (unsigned)(s & 3ull);
                    if (f == 0) continue;
                    run += (long long)(s >> 2);
                    if (f == 2) break;
                    j--;
                }
                excl = (int)run;
                atomicExch(&g_scan_state[b], ((unsigned long long)(excl + total) << 2) | 2ull);
            }
            sexcl = excl;
        }
        __syncthreads();
        int i2 = b * 1024 + t;
        if (i2 < N_NODES) {
            int rp = sexcl + sh[t] - g_deg[i2];
            g_rowptr[i2] = rp;
            g_cursor[i2] = rp;
            g_invdeg[i2] = 1.0f / fmaxf((float)g_deg[i2], 1.0f);
        }
        __syncthreads();
        if (t == 0) {
            __threadfence();
            atomicAdd(&g_scan_done, 1);
        }
    } else {
        if (t == 0) {
            while (atomicAdd(&g_scan_done, 0) < SCAN_BLOCKS) { }
        }
        __syncthreads();
        __threadfence();
        int e = (b - SCAN_BLOCKS) * 1024 + t;
        if (e < N_EDGES) {
            int s = src[e];
            int pos = atomicAdd(&g_cursor[dst[e]], 1);
            g_csr_src[pos] = s;
            g_csr_esrc[pos] = entity[s];
            int ty = etype[e];
            float n = enorm[e];
            float4 a1 = att1[ty];
            float4 a2 = att2[ty];
            g_coeff1[pos] = make_float4(a1.x * n, a1.y * n, a1.z * n, a1.w * n);
            g_coeff2[pos] = make_float4(a2.x * n, a2.y * n, a2.z * n, a2.w * n);
        }
    }
}

// ---------------- aggregation core (R4/R8-proven) ----------------
__device__ __forceinline__ void agg_node(int node, int lane,
                                         const float4* __restrict__ X4,
                                         const int* __restrict__ sidx,
                                         const float4* __restrict__ cf,
                                         float4& s0, float4& s1, float4& s2, float4& s3) {
    int beg = g_rowptr[node], end = g_rowptr[node + 1];
    int p = beg;
    for (; p + 2 <= end; p += 2) {
        float4 ca = cf[p];
        float4 cb = cf[p + 1];
        int sa = sidx[p];
        int sb = sidx[p + 1];
        float4 xa = X4[(size_t)sa * 32 + lane];
        float4 xb = X4[(size_t)sb * 32 + lane];
        s0.x = fmaf(ca.x, xa.x, s0.x); s0.y = fmaf(ca.x, xa.y, s0.y);
        s0.z = fmaf(ca.x, xa.z, s0.z); s0.w = fmaf(ca.x, xa.w, s0.w);
        s1.x = fmaf(ca.y, xa.x, s1.x); s1.y = fmaf(ca.y, xa.y, s1.y);
        s1.z = fmaf(ca.y, xa.z, s1.z); s1.w = fmaf(ca.y, xa.w, s1.w);
        s2.x = fmaf(ca.z, xa.x, s2.x); s2.y = fmaf(ca.z, xa.y, s2.y);
        s2.z = fmaf(ca.z, xa.z, s2.z); s2.w = fmaf(ca.z, xa.w, s2.w);
        s3.x = fmaf(ca.w, xa.x, s3.x); s3.y = fmaf(ca.w, xa.y, s3.y);
        s3.z = fmaf(ca.w, xa.z, s3.z); s3.w = fmaf(ca.w, xa.w, s3.w);
        s0.x = fmaf(cb.x, xb.x, s0.x); s0.y = fmaf(cb.x, xb.y, s0.y);
        s0.z = fmaf(cb.x, xb.z, s0.z); s0.w = fmaf(cb.x, xb.w, s0.w);
        s1.x = fmaf(cb.y, xb.x, s1.x); s1.y = fmaf(cb.y, xb.y, s1.y);
        s1.z = fmaf(cb.y, xb.z, s1.z); s1.w = fmaf(cb.y, xb.w, s1.w);
        s2.x = fmaf(cb.z, xb.x, s2.x); s2.y = fmaf(cb.z, xb.y, s2.y);
        s2.z = fmaf(cb.z, xb.z, s2.z); s2.w = fmaf(cb.z, xb.w, s2.w);
        s3.x = fmaf(cb.w, xb.x, s3.x); s3.y = fmaf(cb.w, xb.y, s3.y);
        s3.z = fmaf(cb.w, xb.z, s3.z); s3.w = fmaf(cb.w, xb.w, s3.w);
    }
    if (p < end) {
        float4 c = cf[p];
        int sn = sidx[p];
        float4 xv = X4[(size_t)sn * 32 + lane];
        s0.x = fmaf(c.x, xv.x, s0.x); s0.y = fmaf(c.x, xv.y, s0.y);
        s0.z = fmaf(c.x, xv.z, s0.z); s0.w = fmaf(c.x, xv.w, s0.w);
        s1.x = fmaf(c.y, xv.x, s1.x); s1.y = fmaf(c.y, xv.y, s1.y);
        s1.z = fmaf(c.y, xv.z, s1.z); s1.w = fmaf(c.y, xv.w, s1.w);
        s2.x = fmaf(c.z, xv.x, s2.x); s2.y = fmaf(c.z, xv.y, s2.y);
        s2.z = fmaf(c.z, xv.z, s2.z); s2.w = fmaf(c.z, xv.w, s2.w);
        s3.x = fmaf(c.w, xv.x, s3.x); s3.y = fmaf(c.w, xv.y, s3.y);
        s3.z = fmaf(c.w, xv.z, s3.z); s3.w = fmaf(c.w, xv.w, s3.w);
    }
}

__device__ __forceinline__ void agg_store(int node, int lane, float d,
                                          float4 s0, float4 s1, float4 s2, float4 s3,
                                          __nv_bfloat16* Ahi, __nv_bfloat16* Alo) {
    s0.x *= d; s0.y *= d; s0.z *= d; s0.w *= d;
    s1.x *= d; s1.y *= d; s1.z *= d; s1.w *= d;
    s2.x *= d; s2.y *= d; s2.z *= d; s2.w *= d;
    s3.x *= d; s3.y *= d; s3.z *= d; s3.w *= d;
    size_t base = (size_t)node * KTOT + 4 * lane;
    uint2 uh, ul;
    pack_hilo(s0.x, s0.y, uh.x, ul.x); pack_hilo(s0.z, s0.w, uh.y, ul.y);
    *(uint2*)(Ahi + base) = uh; *(uint2*)(Alo + base) = ul;
    pack_hilo(s1.x, s1.y, uh.x, ul.x); pack_hilo(s1.z, s1.w, uh.y, ul.y);
    *(uint2*)(Ahi + base + 128) = uh; *(uint2*)(Alo + base + 128) = ul;
    pack_hilo(s2.x, s2.y, uh.x, ul.x); pack_hilo(s2.z, s2.w, uh.y, ul.y);
    *(uint2*)(Ahi + base + 256) = uh; *(uint2*)(Alo + base + 256) = ul;
    pack_hilo(s3.x, s3.y, uh.x, ul.x); pack_hilo(s3.z, s3.w, uh.y, ul.y);
    *(uint2*)(Ahi + base + 384) = uh; *(uint2*)(Alo + base + 384) = ul;
}

// ---------------- 3: layer-1 aggregation ----------------
__global__ void k_agg0(const float4* __restrict__ tbl, const int* __restrict__ entity) {
    int gw = (blockIdx.x * blockDim.x + threadIdx.x) >> 5;
    int lane = threadIdx.x & 31;
    if (gw >= N_NODES) return;
    float4 s0 = make_float4(0.f, 0.f, 0.f, 0.f);
    float4 s1 = s0, s2 = s0, s3 = s0;
    agg_node(gw, lane, tbl, g_csr_esrc, g_coeff1, s0, s1, s2, s3);
    agg_store(gw, lane, g_invdeg[gw], s0, s1, s2, s3, g_A1hi, g_A1lo);
    float4 xs = tbl[(size_t)entity[gw] * 32 + lane];
    size_t a = (size_t)gw * KTOT + 512 + 4 * lane;
    uint2 uh, ul;
    pack_hilo(xs.x, xs.y, uh.x, ul.x); pack_hilo(xs.z, xs.w, uh.y, ul.y);
    *(uint2*)(g_A1hi + a) = uh; *(uint2*)(g_A1lo + a) = ul;
}

// ---------------- 5: layer-2 aggregation + relation_emb + cleanup ----------------
#define REL_BLOCKS 32
#define CLEAN_BLOCKS 391
__global__ void k_agg1(const float* __restrict__ rel, float* __restrict__ out) {
    if (blockIdx.x >= AGG_BLOCKS + REL_BLOCKS) {
        int i = (blockIdx.x - AGG_BLOCKS - REL_BLOCKS) * 256 + threadIdx.x;
        if (i < N_NODES) g_deg[i] = 0;
        if (i < SCAN_BLOCKS) g_scan_state[i] = 0ull;
        if (i == 0) { g_ticket = 0; g_scan_done = 0; }
        return;
    }
    if (blockIdx.x >= AGG_BLOCKS) {
        int i = (blockIdx.x - AGG_BLOCKS) * 256 + threadIdx.x;
        for (; i < 500 * 128; i += REL_BLOCKS * 256)
            out[(size_t)N_NODES * 128 + i] = rel[i];
        return;
    }
    int gw = (blockIdx.x * blockDim.x + threadIdx.x) >> 5;
    int lane = threadIdx.x & 31;
    if (gw >= N_NODES) return;
    float4 s0 = make_float4(0.f, 0.f, 0.f, 0.f);
    float4 s1 = s0, s2 = s0, s3 = s0;
    agg_node(gw, lane, (const float4*)g_h1, g_csr_src, g_coeff2, s0, s1, s2, s3);
    agg_store(gw, lane, g_invdeg[gw], s0, s1, s2, s3, g_A2hi, g_A2lo);
}

// ---------------- 4/6: HMMA GEMM, CTA tile 64x128, 3 CTAs/SM target ----------------
#define A_TB 5120                       // A tile bytes (64 rows x 80B) per hi/lo
#define B_TB 10240                      // B tile bytes (128 rows x 80B) per hi/lo
#define STAGE_B (2 * A_TB + 2 * B_TB)   // 30720
#define SMEM_GEMM (2 * STAGE_B)         // 61440 -> 3 CTAs/SM by smem

__global__ __launch_bounds__(256, 3) void k_gemm_mma(
    int layer, const float* __restrict__ bias, float* __restrict__ out_param, int do_relu)
{
    extern __shared__ char smem[];
    uint32_t sbase = smem_u32(smem);
    const __nv_bfloat16* Ahi = (layer == 0) ? g_A1hi : g_A2hi;
    const __nv_bfloat16* Alo = (layer == 0) ? g_A1lo : g_A2lo;
    const __nv_bfloat16* Whi = (layer == 0) ? g_Whi : g_W2hi;
    const __nv_bfloat16* Wlo = (layer == 0) ? g_Wlo : g_W2lo;
    float* out = (layer == 0) ? g_h1 : out_param;

    int tid = threadIdx.x;
    int wid = tid >> 5;
    int lane = tid & 31;
    int bm = blockIdx.x * 64;
    int wm0 = (wid >> 2) * 32;   // 2 M-groups of 32 rows
    int wn0 = (wid & 3) * 32;    // 4 N-groups of 32 cols

    float acc[2][4][4];
    #pragma unroll
    for (int i = 0; i < 2; i++)
        #pragma unroll
        for (int j = 0; j < 4; j++)
            #pragma unroll
            for (int q = 0; q < 4; q++) acc[i][j][q] = 0.f;

    // loader indices: A 1 chunk/thread per hi/lo, B 2 chunks/thread per hi/lo
    int ar = tid >> 2, ac = tid & 3;       // A row 0..63, 16B chunk 0..3
    int br = tid >> 1;                     // B row 0..127
    int gmrA = bm + ar; if (gmrA >= N_NODES) gmrA = 0;
    uint32_t a_off = (uint32_t)(lane & 15) * 80 + (uint32_t)(lane >> 4) * 16;
    int bg = lane >> 3;
    uint32_t b_off = (uint32_t)((bg >> 1) * 8 + (lane & 7)) * 80 + (uint32_t)(bg & 1) * 16;

    auto load_chunk = [&](int ch, int buf) {
        int kc = ch * 32;
        uint32_t bo = sbase + buf * STAGE_B;
        uint32_t dofA = (uint32_t)ar * 80 + ac * 16;
        int eofA = kc + ac * 8;
        cp16(bo + dofA,        Ahi + (size_t)gmrA * KTOT + eofA);
        cp16(bo + A_TB + dofA, Alo + (size_t)gmrA * KTOT + eofA);
        #pragma unroll
        for (int c = 0; c < 2; c++) {
            int bc = (tid & 1) * 2 + c;
            uint32_t dofB = (uint32_t)br * 80 + bc * 16;
            int eofB = kc + bc * 8;
            cp16(bo + 2 * A_TB + dofB,        Whi + br * KTOT + eofB);
            cp16(bo + 2 * A_TB + B_TB + dofB, Wlo + br * KTOT + eofB);
        }
    };

    load_chunk(0, 0);
    CP_COMMIT();

    #pragma unroll 1
    for (int ch = 0; ch < 20; ch++) {
        int buf = ch & 1;
        if (ch < 19) {
            load_chunk(ch + 1, buf ^ 1);
            CP_COMMIT();
            CP_WAIT(1);
        } else {
            CP_WAIT(0);
        }
        __syncthreads();

        uint32_t a_hi_base = sbase + buf * STAGE_B;
        uint32_t a_lo_base = a_hi_base + A_TB;
        uint32_t b_hi_base = a_hi_base + 2 * A_TB;
        uint32_t b_lo_base = b_hi_base + B_TB;

        #pragma unroll
        for (int kk = 0; kk < 2; kk++) {
            uint32_t kb = (uint32_t)kk * 32;
            uint32_t ahi[2][4], alo[2][4];
            #pragma unroll
            for (int mf = 0; mf < 2; mf++) {
                uint32_t o = (uint32_t)(wm0 + mf * 16) * 80 + a_off + kb;
                ldm_x4(ahi[mf], a_hi_base + o);
                ldm_x4(alo[mf], a_lo_base + o);
            }
            uint32_t bhi[4][2], blo[4][2];
            #pragma unroll
            for (int pr = 0; pr < 2; pr++) {
                uint32_t o = (uint32_t)(wn0 + pr * 16) * 80 + b_off + kb;
                uint32_t th[4], tl[4];
                ldm_x4(th, b_hi_base + o);
                ldm_x4(tl, b_lo_base + o);
                bhi[pr * 2][0] = th[0]; bhi[pr * 2][1] = th[1];
                bhi[pr * 2 + 1][0] = th[2]; bhi[pr * 2 + 1][1] = th[3];
                blo[pr * 2][0] = tl[0]; blo[pr * 2][1] = tl[1];
                blo[pr * 2 + 1][0] = tl[2]; blo[pr * 2 + 1][1] = tl[3];
            }
            #pragma unroll
            for (int mf = 0; mf < 2; mf++)
                #pragma unroll
                for (int nf = 0; nf < 4; nf++)
                    mma16816(acc[mf][nf], ahi[mf], bhi[nf]);
            #pragma unroll
            for (int mf = 0; mf < 2; mf++)
                #pragma unroll
                for (int nf = 0; nf < 4; nf++)
                    mma16816(acc[mf][nf], ahi[mf], blo[nf]);
            #pragma unroll
            for (int mf = 0; mf < 2; mf++)
                #pragma unroll
                for (int nf = 0; nf < 4; nf++)
                    mma16816(acc[mf][nf], alo[mf], bhi[nf]);
        }
        __syncthreads();
    }

    int qm = lane >> 2;
    int qn = (lane & 3) * 2;
    #pragma unroll
    for (int nf = 0; nf < 4; nf++) {
        int n = wn0 + nf * 8 + qn;
        float b0 = bias[n], b1 = bias[n + 1];
        #pragma unroll
        for (int mf = 0; mf < 2; mf++) {
            int m0 = bm + wm0 + mf * 16 + qm;
            float2 lo = make_float2(acc[mf][nf][0] + b0, acc[mf][nf][1] + b1);
            float2 hi = make_float2(acc[mf][nf][2] + b0, acc[mf][nf][3] + b1);
            if (do_relu) {
                lo.x = fmaxf(lo.x, 0.f); lo.y = fmaxf(lo.y, 0.f);
                hi.x = fmaxf(hi.x, 0.f); hi.y = fmaxf(hi.y, 0.f);
            }
            if (m0 < N_NODES) {
                *(float2*)(out + (size_t)m0 * 128 + n) = lo;
                if (layer == 0) {
                    size_t a = (size_t)m0 * KTOT + 512 + n;
                    uint32_t uh, ul;
                    pack_hilo(lo.x, lo.y, uh, ul);
                    *(uint32_t*)(g_A2hi + a) = uh;
                    *(uint32_t*)(g_A2lo + a) = ul;
                }
            }
            if (m0 + 8 < N_NODES) {
                *(float2*)(out + (size_t)(m0 + 8) * 128 + n) = hi;
                if (layer == 0) {
                    size_t a = (size_t)(m0 + 8) * KTOT + 512 + n;
                    uint32_t uh, ul;
                    pack_hilo(hi.x, hi.y, uh, ul);
                    *(uint32_t*)(g_A2hi + a) = uh;
                    *(uint32_t*)(g_A2lo + a) = ul;
                }
            }
        }
    }
}

// ---------------- launch ----------------
extern "C" void kernel_launch(void* const* d_in, const int* in_sizes, int n_in,
                              void* d_out, int out_size) {
    const int*   entity       = (const int*)d_in[0];
    const int*   edge_index   = (const int*)d_in[1];
    const int*   edge_type    = (const int*)d_in[2];
    const float* edge_norm    = (const float*)d_in[3];
    // d_in[4] = DAD_rel (unused by reference output)
    const float* entity_table = (const float*)d_in[5];
    const float* relation_emb = (const float*)d_in[6];
    const float* basis1 = (const float*)d_in[7];
    const float* att1   = (const float*)d_in[8];
    const float* root1  = (const float*)d_in[9];
    const float* bias1  = (const float*)d_in[10];
    const float* basis2 = (const float*)d_in[11];
    const float* att2   = (const float*)d_in[12];
    const float* root2  = (const float*)d_in[13];
    const float* bias2  = (const float*)d_in[14];

    const int* src = edge_index;
    const int* dst = edge_index + N_EDGES;
    float* out = (float*)d_out;

    static int smem_set = 0;
    if (!smem_set) {
        cudaFuncSetAttribute(k_gemm_mma, cudaFuncAttributeMaxDynamicSharedMemorySize, SMEM_GEMM);
        smem_set = 1;
    }

    int gemm_blocks = (N_NODES + 63) / 64;   // 1563

    // 1: histogram + weight split
    k_hist_prepw<<<(N_EDGES + 255) / 256, 256>>>(dst, basis1, root1, basis2, root2);
    // 2: fused scan + scatter
    k_csr<<<SCAN_BLOCKS + SCAT_BLOCKS, 1024>>>(dst, src, entity, edge_type, edge_norm,
                                               (const float4*)att1, (const float4*)att2);
    // 3: layer-1 aggregation
    k_agg0<<<AGG_BLOCKS, 256>>>((const float4*)entity_table, entity);
    // 4: layer-1 GEMM (relu) -> h1 + A2 root cols   [PROFILED SLOT]
    k_gemm_mma<<<gemm_blocks, 256, SMEM_GEMM>>>(0, bias1, nullptr, 1);
    // 5: layer-2 aggregation + relation_emb + cleanup
    k_agg1<<<AGG_BLOCKS + REL_BLOCKS + CLEAN_BLOCKS, 256>>>(relation_emb, out);
    // 6: layer-2 GEMM (no relu) -> d_out
    k_gemm_mma<<<gemm_blocks, 256, SMEM_GEMM>>>(1, bias2, out, 0);
}